// round 3
// baseline (speedup 1.0000x reference)
#include <cuda_runtime.h>
#include <cuda_bf16.h>
#include <cstdint>
#include <cstddef>

#define M_TOTAL 8192
#define IN_F    4096
#define OUT_F   11008
#define BM      128
#define BN      128
#define BKB     64                 /* int8 K-bytes per chunk */
#define NCH     (IN_F / BKB)       /* 64 */
#define GT      512                /* gemm threads, 16 warps */

#define STRIDE  80                 /* padded smem row: conflict-free ldmatrix */
#define S_AHI   0
#define S_ALO   (BM * STRIDE)      /* 10240 */
#define S_B     (2 * BM * STRIDE)  /* 20480 */
#define S_STAGE (3 * BM * STRIDE)  /* 30720 */
#define SMEM_T  (2 * S_STAGE)      /* 61440 */

/* scratch (__device__ globals: alloc-free rule) */
__device__ char  g_q1[(size_t)M_TOTAL * IN_F];
__device__ char  g_q2[(size_t)M_TOTAL * IN_F];
__device__ char  g_w8[(size_t)OUT_F * IN_F];
__device__ float g_sx[M_TOTAL];

static __device__ __forceinline__ uint32_t smem_u32(const void* p) {
    uint32_t a;
    asm("{ .reg .u64 t; cvta.to.shared.u64 t, %1; cvt.u32.u64 %0, t; }"
        : "=r"(a) : "l"(p));
    return a;
}

static __device__ __forceinline__ void cp16(uint32_t dst, const void* src) {
    asm volatile("cp.async.cg.shared.global [%0], [%1], 16;"
                 :: "r"(dst), "l"(src) : "memory");
}

static __device__ __forceinline__ void ldm_x4(uint32_t* r, uint32_t a) {
    asm volatile("ldmatrix.sync.aligned.m8n8.x4.shared.b16 {%0,%1,%2,%3}, [%4];"
                 : "=r"(r[0]), "=r"(r[1]), "=r"(r[2]), "=r"(r[3]) : "r"(a));
}

static __device__ __forceinline__ void imma(int* d, const uint32_t* a,
                                            const uint32_t* b) {
    asm volatile(
        "mma.sync.aligned.m16n8k32.row.col.s32.s8.s8.s32 "
        "{%0,%1,%2,%3}, {%4,%5,%6,%7}, {%8,%9}, {%0,%1,%2,%3};"
        : "+r"(d[0]), "+r"(d[1]), "+r"(d[2]), "+r"(d[3])
        : "r"(a[0]), "r"(a[1]), "r"(a[2]), "r"(a[3]), "r"(b[0]), "r"(b[1]));
}

/* ---------------- phase 1: quantize x (two-level int8) + convert W ------- */

__global__ void k_prep(const float* __restrict__ x, const int* __restrict__ wq) {
    const int t = threadIdx.x;
    if (blockIdx.x < M_TOTAL) {
        /* one block per x row: amax -> s, q1, q2 */
        const int row = blockIdx.x;
        const float4* src = (const float4*)(x + (size_t)row * IN_F) + t * 4;
        float4 v[4];
        v[0] = src[0]; v[1] = src[1]; v[2] = src[2]; v[3] = src[3];

        float am = 0.0f;
#pragma unroll
        for (int i = 0; i < 4; i++) {
            am = fmaxf(am, fabsf(v[i].x)); am = fmaxf(am, fabsf(v[i].y));
            am = fmaxf(am, fabsf(v[i].z)); am = fmaxf(am, fabsf(v[i].w));
        }
#pragma unroll
        for (int o = 16; o > 0; o >>= 1)
            am = fmaxf(am, __shfl_xor_sync(0xFFFFFFFFu, am, o));

        __shared__ float red[8];
        if ((t & 31) == 0) red[t >> 5] = am;
        __syncthreads();
        float amax = red[0];
#pragma unroll
        for (int i = 1; i < 8; i++) amax = fmaxf(amax, red[i]);
        amax = fmaxf(amax, 1e-20f);

        const float s    = amax * (1.0f / 127.0f);
        const float inv1 = 127.0f / amax;
        const float inv2 = 252.0f / s;
        if (t == 0) g_sx[row] = s;

        uint32_t p1[4], p2[4];
#pragma unroll
        for (int i = 0; i < 4; i++) {
            float e[4] = { v[i].x, v[i].y, v[i].z, v[i].w };
            uint32_t w1 = 0, w2 = 0;
#pragma unroll
            for (int j = 0; j < 4; j++) {
                float qf = rintf(e[j] * inv1);
                float rr = fmaf(-s, qf, e[j]);
                int   q1 = (int)qf;
                int   q2 = __float2int_rn(rr * inv2);
                w1 |= (uint32_t)(q1 & 0xFF) << (j * 8);
                w2 |= (uint32_t)(q2 & 0xFF) << (j * 8);
            }
            p1[i] = w1; p2[i] = w2;
        }
        const size_t off = (size_t)row * IN_F + t * 16;
        *(uint4*)(g_q1 + off) = make_uint4(p1[0], p1[1], p1[2], p1[3]);
        *(uint4*)(g_q2 + off) = make_uint4(p2[0], p2[1], p2[2], p2[3]);
    } else {
        /* W int32 -> int8, grid-strided */
        const long n4 = (long)OUT_F * IN_F / 4;
        const long stride = (long)(gridDim.x - M_TOTAL) * blockDim.x;
        for (long i = (long)(blockIdx.x - M_TOTAL) * blockDim.x + t; i < n4;
             i += stride) {
            int4 w = ((const int4*)wq)[i];
            char4 c;
            c.x = (char)w.x; c.y = (char)w.y; c.z = (char)w.z; c.w = (char)w.w;
            ((char4*)g_w8)[i] = c;
        }
    }
}

/* ---------------- phase 2: dual-pass int8 IMMA GEMM ---------------- */

__global__ void __launch_bounds__(GT, 1)
gemm_kernel(float* __restrict__ out, const float* __restrict__ ws) {
    extern __shared__ char smem[];
    const uint32_t sb = smem_u32(smem);
    const int tid = threadIdx.x;
    const int wid = tid >> 5;
    const int lid = tid & 31;
    const int n0 = blockIdx.x * BN;
    const int m0 = blockIdx.y * BM;

    /* warp tile: 32 (m) x 32 (n); warps 4x4 */
    const int wm = (wid & 3) * 32;
    const int wn = (wid >> 2) * 32;

    /* cp.async mapping: 4 threads per row, 16B each */
    const int r = tid >> 2, q = tid & 3;
    const char* gA1 = g_q1 + (size_t)(m0 + r) * IN_F + q * 16;
    const char* gA2 = g_q2 + (size_t)(m0 + r) * IN_F + q * 16;
    const char* gB  = g_w8 + (size_t)(n0 + r) * IN_F + q * 16;
    const uint32_t dst = (uint32_t)r * STRIDE + q * 16;

    /* ldmatrix lane addressing: row = lid&15, k-half = (lid>>4)*16B */
    const int lrow = lid & 15;
    const int lk   = (lid >> 4) * 16;

    int accH[2][4][4], accL[2][4][4];
#pragma unroll
    for (int mf = 0; mf < 2; mf++)
#pragma unroll
        for (int nf = 0; nf < 4; nf++)
#pragma unroll
            for (int j = 0; j < 4; j++) { accH[mf][nf][j] = 0; accL[mf][nf][j] = 0; }

    /* prefetch chunk 0 */
    {
        const uint32_t st = sb;
        cp16(st + S_AHI + dst, gA1);
        cp16(st + S_ALO + dst, gA2);
        cp16(st + S_B   + dst, gB);
        asm volatile("cp.async.commit_group;" ::: "memory");
    }

    for (int c = 0; c < NCH; c++) {
        if (c + 1 < NCH) {
            const uint32_t st = sb + ((c + 1) & 1) * S_STAGE;
            const long ko = (long)(c + 1) * BKB;
            cp16(st + S_AHI + dst, gA1 + ko);
            cp16(st + S_ALO + dst, gA2 + ko);
            cp16(st + S_B   + dst, gB  + ko);
            asm volatile("cp.async.commit_group;" ::: "memory");
            asm volatile("cp.async.wait_group 1;" ::: "memory");
        } else {
            asm volatile("cp.async.wait_group 0;" ::: "memory");
        }
        __syncthreads();

        const uint32_t st = sb + (c & 1) * S_STAGE;
#pragma unroll
        for (int ks = 0; ks < 2; ks++) {
            const int koff = ks * 32 + lk;
            uint32_t ah[2][4], al[2][4], bb[2][4];
#pragma unroll
            for (int mf = 0; mf < 2; mf++) {
                const uint32_t base = st + (uint32_t)(wm + 16 * mf + lrow) * STRIDE + koff;
                ldm_x4(ah[mf], base + S_AHI);
                ldm_x4(al[mf], base + S_ALO);
            }
#pragma unroll
            for (int g = 0; g < 2; g++) {
                const uint32_t base = st + S_B + (uint32_t)(wn + 16 * g + lrow) * STRIDE + koff;
                ldm_x4(bb[g], base);
            }
#pragma unroll
            for (int mf = 0; mf < 2; mf++)
#pragma unroll
                for (int g = 0; g < 2; g++)
#pragma unroll
                    for (int j = 0; j < 2; j++) {
                        uint32_t bp[2] = { bb[g][j], bb[g][j + 2] };
                        imma(accH[mf][g * 2 + j], ah[mf], bp);
                        imma(accL[mf][g * 2 + j], al[mf], bp);
                    }
        }
        __syncthreads();
    }

    /* epilogue: y = ws[n] * (s_m*accH + (s_m/252)*accL) */
    const float i252 = 1.0f / 252.0f;
#pragma unroll
    for (int mf = 0; mf < 2; mf++) {
        const int mrow = m0 + wm + 16 * mf + (lid >> 2);
        const float sa0 = __ldg(g_sx + mrow);
        const float sa1 = __ldg(g_sx + mrow + 8);
#pragma unroll
        for (int nf = 0; nf < 4; nf++) {
            const int n = n0 + wn + nf * 8 + 2 * (lid & 3);
            const float s0 = __ldg(ws + n);
            const float s1 = __ldg(ws + n + 1);
            float2 v;
            v.x = s0 * sa0 * ((float)accH[mf][nf][0] + (float)accL[mf][nf][0] * i252);
            v.y = s1 * sa0 * ((float)accH[mf][nf][1] + (float)accL[mf][nf][1] * i252);
            *(float2*)(out + (size_t)mrow * OUT_F + n) = v;
            v.x = s0 * sa1 * ((float)accH[mf][nf][2] + (float)accL[mf][nf][2] * i252);
            v.y = s1 * sa1 * ((float)accH[mf][nf][3] + (float)accL[mf][nf][3] * i252);
            *(float2*)(out + (size_t)(mrow + 8) * OUT_F + n) = v;
        }
    }
}

extern "C" void kernel_launch(void* const* d_in, const int* in_sizes, int n_in,
                              void* d_out, int out_size) {
    const float* x  = (const float*)d_in[0];
    const int*   wq = (const int*)d_in[1];
    const float* ws = (const float*)d_in[2];
    float* out = (float*)d_out;

    cudaFuncSetAttribute(gemm_kernel, cudaFuncAttributeMaxDynamicSharedMemorySize,
                         SMEM_T);

    k_prep<<<M_TOTAL + 4096, 256>>>(x, wq);

    dim3 grid(OUT_F / BN, M_TOTAL / BM);   /* 86 x 64 */
    gemm_kernel<<<grid, GT, SMEM_T>>>(out, ws);
}

// round 4
// speedup vs baseline: 3.5038x; 3.5038x over previous
#include <cuda_runtime.h>
#include <cuda_fp16.h>
#include <cstdint>
#include <cstddef>

#define M_TOTAL 8192
#define IN_F    4096
#define OUT_F   11008
#define BM      128
#define BN      128
#define BK      64                  /* fp16 K per chunk */
#define NCH     (IN_F / BK)         /* 64 */
#define GT      256                 /* 8 warps */

#define STRIDE  144                 /* bytes per smem row (72 halves, pad) */
#define S_A     0
#define S_B     (BM * STRIDE)       /* 18432 */
#define S_STAGE (2 * BM * STRIDE)   /* 36864 */
#define SMEM_T  (2 * S_STAGE)       /* 73728 */

/* fp16 scratch (__device__ globals: alloc-free rule) */
__device__ __half g_xh[(size_t)M_TOTAL * IN_F];
__device__ __half g_wh[(size_t)OUT_F * IN_F];

static __device__ __forceinline__ uint32_t smem_u32(const void* p) {
    uint32_t a;
    asm("{ .reg .u64 t; cvta.to.shared.u64 t, %1; cvt.u32.u64 %0, t; }"
        : "=r"(a) : "l"(p));
    return a;
}

static __device__ __forceinline__ void cp16(uint32_t dst, const void* src) {
    asm volatile("cp.async.cg.shared.global [%0], [%1], 16;"
                 :: "r"(dst), "l"(src) : "memory");
}

static __device__ __forceinline__ void ldm_x4(uint32_t* r, uint32_t a) {
    asm volatile("ldmatrix.sync.aligned.m8n8.x4.shared.b16 {%0,%1,%2,%3}, [%4];"
                 : "=r"(r[0]), "=r"(r[1]), "=r"(r[2]), "=r"(r[3]) : "r"(a));
}

static __device__ __forceinline__ void mma16816(float* d, const uint32_t* a,
                                                const uint32_t* b) {
    asm volatile(
        "mma.sync.aligned.m16n8k16.row.col.f32.f16.f16.f32 "
        "{%0,%1,%2,%3}, {%4,%5,%6,%7}, {%8,%9}, {%0,%1,%2,%3};"
        : "+f"(d[0]), "+f"(d[1]), "+f"(d[2]), "+f"(d[3])
        : "r"(a[0]), "r"(a[1]), "r"(a[2]), "r"(a[3]), "r"(b[0]), "r"(b[1]));
}

/* ---------------- phase 1: fp16 conversions ---------------- */

__global__ void k_convert_x(const float* __restrict__ x) {
    const long n4 = (long)M_TOTAL * IN_F / 4;
    const long stride = (long)gridDim.x * blockDim.x;
    for (long i = (long)blockIdx.x * blockDim.x + threadIdx.x; i < n4; i += stride) {
        float4 v = ((const float4*)x)[i];
        __half2* p = (__half2*)g_xh;
        p[2 * i]     = __floats2half2_rn(v.x, v.y);
        p[2 * i + 1] = __floats2half2_rn(v.z, v.w);
    }
}

__global__ void k_convert_w(const int* __restrict__ wq) {
    const long n4 = (long)OUT_F * IN_F / 4;
    const long stride = (long)gridDim.x * blockDim.x;
    for (long i = (long)blockIdx.x * blockDim.x + threadIdx.x; i < n4; i += stride) {
        int4 w = ((const int4*)wq)[i];
        __half2* p = (__half2*)g_wh;
        __half2 t;
        t.x = __int2half_rn(w.x); t.y = __int2half_rn(w.y);
        p[2 * i] = t;
        t.x = __int2half_rn(w.z); t.y = __int2half_rn(w.w);
        p[2 * i + 1] = t;
    }
}

/* ---------------- phase 2: single-pass fp16 HMMA GEMM ---------------- */

__global__ void __launch_bounds__(GT, 2)
gemm_kernel(float* __restrict__ out, const float* __restrict__ ws) {
    extern __shared__ char smem[];
    const uint32_t sb = smem_u32(smem);
    const int tid = threadIdx.x;
    const int wid = tid >> 5;
    const int lid = tid & 31;
    const int n0 = blockIdx.x * BN;
    const int m0 = blockIdx.y * BM;

    /* warps 4(m) x 2(n): warp tile 32 x 64 */
    const int wm = (wid & 3) * 32;
    const int wn = (wid >> 2) * 64;

    /* cp.async: 2 threads per 128B row, 64B each */
    const int r = tid >> 1, half = tid & 1;
    const __half* gA = g_xh + (size_t)(m0 + r) * IN_F + half * 32;
    const __half* gB = g_wh + (size_t)(n0 + r) * IN_F + half * 32;
    const uint32_t dst = (uint32_t)r * STRIDE + half * 64;

    const int a_row  = (lid & 7) + ((lid >> 3) & 1) * 8;
    const int a_koff = (lid >> 4) * 8;
    const int b_row  = (lid & 7) + ((lid >> 4) & 1) * 8;
    const int b_koff = ((lid >> 3) & 1) * 8;

    float acc[2][8][4];
#pragma unroll
    for (int mf = 0; mf < 2; mf++)
#pragma unroll
        for (int nf = 0; nf < 8; nf++)
#pragma unroll
            for (int j = 0; j < 4; j++) acc[mf][nf][j] = 0.0f;

    /* prefetch chunk 0 */
#pragma unroll
    for (int i = 0; i < 4; i++) {
        cp16(sb + S_A + dst + i * 16, gA + i * 8);
        cp16(sb + S_B + dst + i * 16, gB + i * 8);
    }
    asm volatile("cp.async.commit_group;" ::: "memory");

    for (int c = 0; c < NCH; c++) {
        if (c + 1 < NCH) {
            const uint32_t st = sb + ((c + 1) & 1) * S_STAGE;
            const long ko = (long)(c + 1) * BK;
#pragma unroll
            for (int i = 0; i < 4; i++) {
                cp16(st + S_A + dst + i * 16, gA + ko + i * 8);
                cp16(st + S_B + dst + i * 16, gB + ko + i * 8);
            }
            asm volatile("cp.async.commit_group;" ::: "memory");
            asm volatile("cp.async.wait_group 1;" ::: "memory");
        } else {
            asm volatile("cp.async.wait_group 0;" ::: "memory");
        }
        __syncthreads();

        const uint32_t st = sb + (c & 1) * S_STAGE;
#pragma unroll
        for (int kk = 0; kk < 4; kk++) {
            const int ke = kk * 16;
            uint32_t ah[2][4], bb[16];
#pragma unroll
            for (int mf = 0; mf < 2; mf++) {
                uint32_t base = st + S_A + (uint32_t)(wm + 16 * mf + a_row) * STRIDE
                                + (ke + a_koff) * 2;
                ldm_x4(ah[mf], base);
            }
#pragma unroll
            for (int nf4 = 0; nf4 < 4; nf4++) {
                uint32_t addr = st + S_B + (uint32_t)(wn + 16 * nf4 + b_row) * STRIDE
                                + (ke + b_koff) * 2;
                ldm_x4(&bb[nf4 * 4], addr);
            }
#pragma unroll
            for (int mf = 0; mf < 2; mf++)
#pragma unroll
                for (int nf = 0; nf < 8; nf++) {
                    const uint32_t* bp = &bb[(nf >> 1) * 4 + (nf & 1) * 2];
                    mma16816(acc[mf][nf], ah[mf], bp);
                }
        }
        __syncthreads();
    }

    /* epilogue: y = acc * ws[n] */
#pragma unroll
    for (int nf = 0; nf < 8; nf++) {
        const int n = n0 + wn + nf * 8 + 2 * (lid & 3);
        const float s0 = __ldg(ws + n);
        const float s1 = __ldg(ws + n + 1);
#pragma unroll
        for (int mf = 0; mf < 2; mf++) {
            const int mrow = m0 + wm + 16 * mf + (lid >> 2);
            float2 v0, v1;
            v0.x = acc[mf][nf][0] * s0;
            v0.y = acc[mf][nf][1] * s1;
            v1.x = acc[mf][nf][2] * s0;
            v1.y = acc[mf][nf][3] * s1;
            *(float2*)(out + (size_t)mrow * OUT_F + n) = v0;
            *(float2*)(out + (size_t)(mrow + 8) * OUT_F + n) = v1;
        }
    }
}

extern "C" void kernel_launch(void* const* d_in, const int* in_sizes, int n_in,
                              void* d_out, int out_size) {
    const float* x  = (const float*)d_in[0];
    const int*   wq = (const int*)d_in[1];
    const float* ws = (const float*)d_in[2];
    float* out = (float*)d_out;

    cudaFuncSetAttribute(gemm_kernel, cudaFuncAttributeMaxDynamicSharedMemorySize,
                         SMEM_T);

    k_convert_x<<<4096, 256>>>(x);
    k_convert_w<<<4096, 256>>>(wq);

    dim3 grid(OUT_F / BN, M_TOTAL / BM);   /* 86 x 64 */
    gemm_kernel<<<grid, GT, SMEM_T>>>(out, ws);
}